// round 1
// baseline (speedup 1.0000x reference)
#include <cuda_runtime.h>
#include <math.h>

#define H 16
#define DMODEL 1024
#define DK 64
#define NB 2
#define SEQ 2048
#define MROWS (NB*SEQ)   // 4096
#define BHN (NB*H)       // 32

// Scratch (device globals — no allocation allowed)
__device__ float g_q[BHN * SEQ * DK];     // 16 MB, head-major [bh][s][d]
__device__ float g_k[BHN * SEQ * DK];
__device__ float g_v[BHN * SEQ * DK];
__device__ float g_ctx[MROWS * DMODEL];   // 16 MB, [b*S+s][h*64+d]

// ---------------------------------------------------------------------------
// GEMM: Y = X (M x K) @ W^T (N x K) + bias.   M=4096, N=K=1024.
// MODE 0: Y[m*N + n]   (final projection, Y = d_out)
// MODE 1: head layout  Y[((b*H + h)*SEQ + s)*DK + d]  (q/k/v projections)
// 64x64 block tile, BK=16, 256 threads, 4x4 microtile per thread.
// ---------------------------------------------------------------------------
template <int MODE>
__global__ void gemm_kernel(const float* __restrict__ X,
                            const float* __restrict__ W,
                            const float* __restrict__ bias,
                            float* __restrict__ Y)
{
    const int K = DMODEL, N = DMODEL;
    __shared__ float As[64 * 20];   // [m][k] row-major, padded row = 20 floats
    __shared__ float Bs[16 * 64];   // [k][n] (k-major)

    const int tid = threadIdx.x;
    const int tx = tid & 15, ty = tid >> 4;
    const int m0 = blockIdx.y * 64, n0 = blockIdx.x * 64;
    const int lr = tid >> 2;            // load row 0..63
    const int lc = (tid & 3) << 2;      // load col (float4) 0,4,8,12

    float acc[4][4];
#pragma unroll
    for (int i = 0; i < 4; i++)
#pragma unroll
        for (int j = 0; j < 4; j++) acc[i][j] = 0.0f;

    for (int k0 = 0; k0 < K; k0 += 16) {
        float4 xa = *(const float4*)&X[(m0 + lr) * K + k0 + lc];
        float4 wb = *(const float4*)&W[(n0 + lr) * K + k0 + lc];
        __syncthreads();
        *(float4*)&As[lr * 20 + lc] = xa;
        Bs[(lc + 0) * 64 + lr] = wb.x;
        Bs[(lc + 1) * 64 + lr] = wb.y;
        Bs[(lc + 2) * 64 + lr] = wb.z;
        Bs[(lc + 3) * 64 + lr] = wb.w;
        __syncthreads();

#pragma unroll
        for (int kk = 0; kk < 16; kk += 4) {
            float a[4][4];
#pragma unroll
            for (int i = 0; i < 4; i++) {
                float4 t = *(float4*)&As[(4 * ty + i) * 20 + kk];
                a[i][0] = t.x; a[i][1] = t.y; a[i][2] = t.z; a[i][3] = t.w;
            }
#pragma unroll
            for (int u = 0; u < 4; u++) {
                float4 b4 = *(float4*)&Bs[(kk + u) * 64 + 4 * tx];
                float bb0 = b4.x, bb1 = b4.y, bb2 = b4.z, bb3 = b4.w;
#pragma unroll
                for (int i = 0; i < 4; i++) {
                    acc[i][0] = fmaf(a[i][u], bb0, acc[i][0]);
                    acc[i][1] = fmaf(a[i][u], bb1, acc[i][1]);
                    acc[i][2] = fmaf(a[i][u], bb2, acc[i][2]);
                    acc[i][3] = fmaf(a[i][u], bb3, acc[i][3]);
                }
            }
        }
    }

    float4 bias4 = *(const float4*)&bias[n0 + 4 * tx];
#pragma unroll
    for (int i = 0; i < 4; i++) {
        int m = m0 + 4 * ty + i;
        float4 o;
        o.x = acc[i][0] + bias4.x;
        o.y = acc[i][1] + bias4.y;
        o.z = acc[i][2] + bias4.z;
        o.w = acc[i][3] + bias4.w;
        if (MODE == 0) {
            *(float4*)&Y[m * N + n0 + 4 * tx] = o;
        } else {
            int b = m >> 11, s = m & 2047;
            int h = n0 >> 6;                  // whole 64-col tile is one head
            *(float4*)&Y[((b * H + h) * SEQ + s) * DK + 4 * tx] = o;
        }
    }
}

// ---------------------------------------------------------------------------
// Flash attention: per (bh, q-tile of 64). d_k = 64, KV tile = 64.
// Q and K stored transposed [d][row] with XOR swizzle for conflict-free
// float4 reads. V row-major. Online softmax, 16-lane shfl reductions.
// Static smem = 48 KB exactly (K/V share a buffer).
// ---------------------------------------------------------------------------
__device__ __forceinline__ float redmax16(float v) {
#pragma unroll
    for (int o = 8; o; o >>= 1) v = fmaxf(v, __shfl_xor_sync(0xffffffffu, v, o, 16));
    return v;
}
__device__ __forceinline__ float redsum16(float v) {
#pragma unroll
    for (int o = 8; o; o >>= 1) v += __shfl_xor_sync(0xffffffffu, v, o, 16);
    return v;
}

__global__ void attn_kernel()
{
    __shared__ float Qst[64 * 64];   // swizzled transposed [d][r]
    __shared__ float KVs[64 * 64];   // K: swizzled transposed; then V: row-major
    __shared__ float Ps[64 * 64];    // probs [r][k]

    const int bh = blockIdx.x;
    const int q0 = blockIdx.y << 6;
    const int tid = threadIdx.x;
    const int tx = tid & 15, ty = tid >> 4;

    const float* qg = g_q + (bh * SEQ + q0) * DK;
    const float* kg = g_k + bh * SEQ * DK;
    const float* vg = g_v + bh * SEQ * DK;

    // Load Q: element (r, d) -> Qst[d*64 + (r ^ ((d&15)<<2))]
#pragma unroll
    for (int t = 0; t < 4; t++) {
        int idx = tid + t * 256;             // float4 index, 1024 total
        int r = idx >> 4;
        int dq = (idx & 15) << 2;
        float4 v4 = *(const float4*)&qg[r * DK + dq];
        float vv[4] = {v4.x, v4.y, v4.z, v4.w};
#pragma unroll
        for (int u = 0; u < 4; u++) {
            int d = dq + u;
            Qst[d * 64 + (r ^ ((d & 15) << 2))] = vv[u];
        }
    }

    float mrow[4], lrow[4], acc[4][4];
#pragma unroll
    for (int i = 0; i < 4; i++) {
        mrow[i] = -1e30f; lrow[i] = 0.0f;
#pragma unroll
        for (int j = 0; j < 4; j++) acc[i][j] = 0.0f;
    }
    __syncthreads();

    for (int kt = 0; kt < SEQ; kt += 64) {
        // ---- load K tile, swizzled transposed ----
#pragma unroll
        for (int t = 0; t < 4; t++) {
            int idx = tid + t * 256;
            int r = idx >> 4;
            int dq = (idx & 15) << 2;
            float4 k4 = *(const float4*)&kg[(kt + r) * DK + dq];
            float kk[4] = {k4.x, k4.y, k4.z, k4.w};
#pragma unroll
            for (int u = 0; u < 4; u++) {
                int d = dq + u;
                KVs[d * 64 + (r ^ ((d & 15) << 2))] = kk[u];
            }
        }
        __syncthreads();

        // ---- scores S = Q K^T / 8 ----
        float s[4][4];
#pragma unroll
        for (int i = 0; i < 4; i++)
#pragma unroll
            for (int j = 0; j < 4; j++) s[i][j] = 0.0f;

#pragma unroll 4
        for (int d = 0; d < 64; d++) {
            int swz = (d & 15) << 2;
            float4 q4 = *(float4*)&Qst[d * 64 + ((4 * ty) ^ swz)];
            float4 k4 = *(float4*)&KVs[d * 64 + ((4 * tx) ^ swz)];
            float qa[4] = {q4.x, q4.y, q4.z, q4.w};
            float ka[4] = {k4.x, k4.y, k4.z, k4.w};
#pragma unroll
            for (int i = 0; i < 4; i++)
#pragma unroll
                for (int j = 0; j < 4; j++)
                    s[i][j] = fmaf(qa[i], ka[j], s[i][j]);
        }

        // ---- online softmax update + write P ----
#pragma unroll
        for (int i = 0; i < 4; i++) {
            float tm = -1e30f;
#pragma unroll
            for (int j = 0; j < 4; j++) { s[i][j] *= 0.125f; tm = fmaxf(tm, s[i][j]); }
            tm = redmax16(tm);
            float mn = fmaxf(mrow[i], tm);
            float al = __expf(mrow[i] - mn);
            float rs = 0.0f;
#pragma unroll
            for (int j = 0; j < 4; j++) { s[i][j] = __expf(s[i][j] - mn); rs += s[i][j]; }
            rs = redsum16(rs);
            lrow[i] = lrow[i] * al + rs;
            mrow[i] = mn;
#pragma unroll
            for (int j = 0; j < 4; j++) acc[i][j] *= al;
            float4 p4; p4.x = s[i][0]; p4.y = s[i][1]; p4.z = s[i][2]; p4.w = s[i][3];
            *(float4*)&Ps[(4 * ty + i) * 64 + 4 * tx] = p4;
        }
        __syncthreads();   // P visible; everyone done reading K

        // ---- load V tile (row-major) into same buffer ----
#pragma unroll
        for (int t = 0; t < 4; t++) {
            int idx = tid + t * 256;
            int r = idx >> 4;
            int dq = (idx & 15) << 2;
            float4 v4 = *(const float4*)&vg[(kt + r) * DK + dq];
            *(float4*)&KVs[r * DK + dq] = v4;
        }
        __syncthreads();

        // ---- acc += P V ----
#pragma unroll 4
        for (int k = 0; k < 64; k++) {
            float4 v4 = *(float4*)&KVs[k * 64 + 4 * tx];
#pragma unroll
            for (int i = 0; i < 4; i++) {
                float p = Ps[(4 * ty + i) * 64 + k];
                acc[i][0] = fmaf(p, v4.x, acc[i][0]);
                acc[i][1] = fmaf(p, v4.y, acc[i][1]);
                acc[i][2] = fmaf(p, v4.z, acc[i][2]);
                acc[i][3] = fmaf(p, v4.w, acc[i][3]);
            }
        }
        __syncthreads();   // done with V & P before next tile overwrites
    }

    // ---- epilogue: ctx = acc / l, merged-head layout ----
    const int b = bh >> 4, h = bh & 15;
#pragma unroll
    for (int i = 0; i < 4; i++) {
        float inv = 1.0f / lrow[i];
        int row = q0 + 4 * ty + i;
        float4 o;
        o.x = acc[i][0] * inv; o.y = acc[i][1] * inv;
        o.z = acc[i][2] * inv; o.w = acc[i][3] * inv;
        *(float4*)&g_ctx[(b * SEQ + row) * DMODEL + h * 64 + 4 * tx] = o;
    }
}

// ---------------------------------------------------------------------------
extern "C" void kernel_launch(void* const* d_in, const int* in_sizes, int n_in,
                              void* d_out, int out_size)
{
    (void)in_sizes; (void)n_in; (void)out_size;
    const float* q  = (const float*)d_in[0];
    const float* k  = (const float*)d_in[1];
    const float* v  = (const float*)d_in[2];
    const float* Wq = (const float*)d_in[3];
    const float* bq = (const float*)d_in[4];
    const float* Wk = (const float*)d_in[5];
    const float* bk = (const float*)d_in[6];
    const float* Wv = (const float*)d_in[7];
    const float* bv = (const float*)d_in[8];
    const float* Wo = (const float*)d_in[9];
    const float* bo = (const float*)d_in[10];
    float* out = (float*)d_out;

    float *gq, *gk, *gv, *gctx;
    cudaGetSymbolAddress((void**)&gq,   g_q);
    cudaGetSymbolAddress((void**)&gk,   g_k);
    cudaGetSymbolAddress((void**)&gv,   g_v);
    cudaGetSymbolAddress((void**)&gctx, g_ctx);

    dim3 gg(DMODEL / 64, MROWS / 64);   // (16, 64)
    gemm_kernel<1><<<gg, 256>>>(q, Wq, bq, gq);
    gemm_kernel<1><<<gg, 256>>>(k, Wk, bk, gk);
    gemm_kernel<1><<<gg, 256>>>(v, Wv, bv, gv);

    attn_kernel<<<dim3(BHN, SEQ / 64), 256>>>();

    gemm_kernel<0><<<gg, 256>>>(gctx, Wo, bo, out);
}

// round 3
// speedup vs baseline: 1.3408x; 1.3408x over previous
#include <cuda_runtime.h>
#include <cuda_bf16.h>
#include <cstdint>
#include <math.h>

#define H 16
#define DMODEL 1024
#define DK 64
#define NB 2
#define SEQ 2048
#define MROWS (NB*SEQ)   // 4096
#define BHN (NB*H)       // 32

// ---------------- scratch (device globals; no allocation allowed) ----------
__device__ float g_q[BHN * SEQ * DK];
__device__ float g_k[BHN * SEQ * DK];
__device__ float g_v[BHN * SEQ * DK];
__device__ float g_ctx[MROWS * DMODEL];

__device__ __nv_bfloat16 s_qh[MROWS * DMODEL], s_ql[MROWS * DMODEL];
__device__ __nv_bfloat16 s_kh[MROWS * DMODEL], s_kl[MROWS * DMODEL];
__device__ __nv_bfloat16 s_vh[MROWS * DMODEL], s_vl[MROWS * DMODEL];
__device__ __nv_bfloat16 s_ch[MROWS * DMODEL], s_cl[MROWS * DMODEL];
__device__ __nv_bfloat16 s_wh[4][DMODEL * DMODEL], s_wl[4][DMODEL * DMODEL];

// ---------------- helpers ---------------------------------------------------
static __device__ __forceinline__ uint32_t smem_u32(const void* p) {
    uint32_t a;
    asm("{ .reg .u64 t; cvta.to.shared.u64 t, %1; cvt.u32.u64 %0, t; }"
        : "=r"(a) : "l"(p));
    return a;
}
static __device__ __forceinline__ void cp16(uint32_t s, const void* g) {
    asm volatile("cp.async.cg.shared.global [%0], [%1], 16;" :: "r"(s), "l"(g));
}
#define CP_COMMIT() asm volatile("cp.async.commit_group;")
template <int N>
static __device__ __forceinline__ void cp_wait() {
    asm volatile("cp.async.wait_group %0;" :: "n"(N));
}
static __device__ __forceinline__ void ldm_x4(uint32_t& r0, uint32_t& r1,
                                              uint32_t& r2, uint32_t& r3, uint32_t a) {
    asm volatile("ldmatrix.sync.aligned.m8n8.x4.shared.b16 {%0,%1,%2,%3}, [%4];"
                 : "=r"(r0), "=r"(r1), "=r"(r2), "=r"(r3) : "r"(a));
}
static __device__ __forceinline__ void mma_bf16(float* c, const uint32_t* a,
                                                const uint32_t* b) {
    asm volatile(
        "mma.sync.aligned.m16n8k16.row.col.f32.bf16.bf16.f32 "
        "{%0,%1,%2,%3}, {%4,%5,%6,%7}, {%8,%9}, {%0,%1,%2,%3};"
        : "+f"(c[0]), "+f"(c[1]), "+f"(c[2]), "+f"(c[3])
        : "r"(a[0]), "r"(a[1]), "r"(a[2]), "r"(a[3]), "r"(b[0]), "r"(b[1]));
}

// ---------------------------------------------------------------------------
// split fp32 -> bf16 hi + bf16 lo (residual)
// ---------------------------------------------------------------------------
__global__ void split_kernel(const float* __restrict__ x,
                             __nv_bfloat16* __restrict__ hi,
                             __nv_bfloat16* __restrict__ lo, int n4)
{
    int i = blockIdx.x * 256 + threadIdx.x;
    if (i >= n4) return;
    float4 v = ((const float4*)x)[i];
    float vv[4] = {v.x, v.y, v.z, v.w};
    __nv_bfloat162 h2[2], l2[2];
#pragma unroll
    for (int u = 0; u < 2; u++) {
        __nv_bfloat16 h0 = __float2bfloat16(vv[2 * u]);
        __nv_bfloat16 h1 = __float2bfloat16(vv[2 * u + 1]);
        __nv_bfloat16 l0 = __float2bfloat16(vv[2 * u] - __bfloat162float(h0));
        __nv_bfloat16 l1 = __float2bfloat16(vv[2 * u + 1] - __bfloat162float(h1));
        h2[u].x = h0; h2[u].y = h1;
        l2[u].x = l0; l2[u].y = l1;
    }
    ((__nv_bfloat162*)hi)[2 * i] = h2[0];
    ((__nv_bfloat162*)hi)[2 * i + 1] = h2[1];
    ((__nv_bfloat162*)lo)[2 * i] = l2[0];
    ((__nv_bfloat162*)lo)[2 * i + 1] = l2[1];
}

// ---------------------------------------------------------------------------
// mma.sync split-bf16 GEMM: Y = A(4096x1024) @ B^T(1024x1024) + bias.
// A = Ah+Al, B = Bh+Bl; passes Ah*Bh, Ah*Bl, Al*Bh (K_eff = 3072).
// 128x128 CTA tile, BK=32 bf16, 8 warps (2m x 4n), warp tile 64x32.
// Smem rows = 64B, XOR-swizzled 16B chunks (chunk ^= row&3): conflict-free
// ldmatrix. cp.async double-buffered, 32KB smem.
// MODE 0: flat [m][n].  MODE 1: head layout [(b*H+h)*SEQ+s]*64+d.
// ---------------------------------------------------------------------------
#define NIT 96

template <int MODE>
__global__ void __launch_bounds__(256, 2)
gemm_mma(const __nv_bfloat16* __restrict__ Ah, const __nv_bfloat16* __restrict__ Al,
         const __nv_bfloat16* __restrict__ Bh, const __nv_bfloat16* __restrict__ Bl,
         const float* __restrict__ bias, float* __restrict__ Y)
{
    __shared__ __align__(128) char smA[2][128 * 64];
    __shared__ __align__(128) char smB[2][128 * 64];

    const int tid = threadIdx.x;
    const int wid = tid >> 5, lane = tid & 31;
    const int wm = wid >> 2, wn = wid & 3;      // 2 x 4 warp grid
    const int m0 = blockIdx.y << 7, n0 = blockIdx.x << 7;

    const uint32_t sA0 = smem_u32(smA[0]), sA1 = smem_u32(smA[1]);
    const uint32_t sB0 = smem_u32(smB[0]), sB1 = smem_u32(smB[1]);

    float acc[4][4][4];
#pragma unroll
    for (int i = 0; i < 4; i++)
#pragma unroll
        for (int j = 0; j < 4; j++)
#pragma unroll
            for (int u = 0; u < 4; u++) acc[i][j][u] = 0.0f;

    // loader: thread handles chunks tid and tid+256 (of 512) for A and B
    const int r0c = tid >> 2, b0c = tid & 3;            // chunk tid
    const int r1c = (tid + 256) >> 2, b1c = tid & 3;    // chunk tid+256
    const uint32_t o0 = (uint32_t)(r0c * 64 + ((b0c ^ (r0c & 3)) << 4));
    const uint32_t o1 = (uint32_t)(r1c * 64 + ((b1c ^ (r1c & 3)) << 4));

    auto load_it = [&](int it, int buf) {
        const int p = it >> 5;
        const int kk = (it & 31) << 5;
        const __nv_bfloat16* Ap = (p < 2) ? Ah : Al;
        const __nv_bfloat16* Bp = (p == 1) ? Bl : Bh;
        uint32_t da = buf ? sA1 : sA0;
        uint32_t db = buf ? sB1 : sB0;
        cp16(da + o0, Ap + (size_t)(m0 + r0c) * DMODEL + kk + b0c * 8);
        cp16(da + o1, Ap + (size_t)(m0 + r1c) * DMODEL + kk + b1c * 8);
        cp16(db + o0, Bp + (size_t)(n0 + r0c) * DMODEL + kk + b0c * 8);
        cp16(db + o1, Bp + (size_t)(n0 + r1c) * DMODEL + kk + b1c * 8);
        CP_COMMIT();
    };

    // ldmatrix lane addressing (within tile, rows relative to warp origin)
    // A (per m-tile mt): row = wm*64 + mt*16 + (lane & 15); chunk = 2ks + (lane>>4)
    // B (per n-pair np): row = wn*32 + np*16 + (lane&7) + ((lane>>4)&1)*8;
    //                    chunk = 2ks + ((lane>>3)&1)
    const int arow = wm * 64 + (lane & 15);
    const int abit = lane >> 4;
    const int brow = wn * 32 + (lane & 7) + ((lane >> 4) & 1) * 8;
    const int bbit = (lane >> 3) & 1;

    load_it(0, 0);

    for (int it = 0; it < NIT; ++it) {
        if (it + 1 < NIT) load_it(it + 1, (it + 1) & 1);
        if (it + 1 < NIT) cp_wait<1>(); else cp_wait<0>();
        __syncthreads();

        const uint32_t da = (it & 1) ? sA1 : sA0;
        const uint32_t db = (it & 1) ? sB1 : sB0;

#pragma unroll
        for (int ks = 0; ks < 2; ks++) {
            uint32_t af[4][4], bf[2][4];
#pragma unroll
            for (int mt = 0; mt < 4; mt++) {
                int row = arow + mt * 16;
                int ch = 2 * ks + abit;
                uint32_t ad = da + (uint32_t)(row * 64 + ((ch ^ (row & 3)) << 4));
                ldm_x4(af[mt][0], af[mt][1], af[mt][2], af[mt][3], ad);
            }
#pragma unroll
            for (int np = 0; np < 2; np++) {
                int row = brow + np * 16;
                int ch = 2 * ks + bbit;
                uint32_t bd = db + (uint32_t)(row * 64 + ((ch ^ (row & 3)) << 4));
                ldm_x4(bf[np][0], bf[np][1], bf[np][2], bf[np][3], bd);
            }
#pragma unroll
            for (int mt = 0; mt < 4; mt++)
#pragma unroll
                for (int nt = 0; nt < 4; nt++)
                    mma_bf16(acc[mt][nt], af[mt], bf[nt >> 1] + (nt & 1) * 2);
        }
        __syncthreads();
    }

    // ---- epilogue ----
    const int ml = lane >> 2;                 // row within m16
    const int nl = (lane & 3) << 1;           // col pair within n8
#pragma unroll
    for (int mt = 0; mt < 4; mt++) {
#pragma unroll
        for (int half = 0; half < 2; half++) {
            int m = m0 + wm * 64 + mt * 16 + ml + half * 8;
#pragma unroll
            for (int nt = 0; nt < 4; nt++) {
                int n = n0 + wn * 32 + nt * 8 + nl;
                float2 o;
                o.x = acc[mt][nt][2 * half + 0] + bias[n + 0];
                o.y = acc[mt][nt][2 * half + 1] + bias[n + 1];
                if (MODE == 0) {
                    *(float2*)&Y[(size_t)m * DMODEL + n] = o;
                } else {
                    int bb = m >> 11, s = m & 2047;
                    int h = n >> 6, d = n & 63;
                    *(float2*)&Y[(size_t)((bb * H + h) * SEQ + s) * DK + d] = o;
                }
            }
        }
    }
}

// ---------------------------------------------------------------------------
// FFMA flash attention (unchanged from R1 passing version)
// ---------------------------------------------------------------------------
__device__ __forceinline__ float redmax16(float v) {
#pragma unroll
    for (int o = 8; o; o >>= 1) v = fmaxf(v, __shfl_xor_sync(0xffffffffu, v, o, 16));
    return v;
}
__device__ __forceinline__ float redsum16(float v) {
#pragma unroll
    for (int o = 8; o; o >>= 1) v += __shfl_xor_sync(0xffffffffu, v, o, 16);
    return v;
}

__global__ void attn_kernel()
{
    __shared__ float Qst[64 * 64];
    __shared__ float KVs[64 * 64];
    __shared__ float Ps[64 * 64];

    const int bh = blockIdx.x;
    const int q0 = blockIdx.y << 6;
    const int tid = threadIdx.x;
    const int tx = tid & 15, ty = tid >> 4;

    const float* qg = g_q + (bh * SEQ + q0) * DK;
    const float* kg = g_k + bh * SEQ * DK;
    const float* vg = g_v + bh * SEQ * DK;

#pragma unroll
    for (int t = 0; t < 4; t++) {
        int idx = tid + t * 256;
        int r = idx >> 4;
        int dq = (idx & 15) << 2;
        float4 v4 = *(const float4*)&qg[r * DK + dq];
        float vv[4] = {v4.x, v4.y, v4.z, v4.w};
#pragma unroll
        for (int u = 0; u < 4; u++) {
            int d = dq + u;
            Qst[d * 64 + (r ^ ((d & 15) << 2))] = vv[u];
        }
    }

    float mrow[4], lrow[4], acc[4][4];
#pragma unroll
    for (int i = 0; i < 4; i++) {
        mrow[i] = -1e30f; lrow[i] = 0.0f;
#pragma unroll
        for (int j = 0; j < 4; j++) acc[i][j] = 0.0f;
    }
    __syncthreads();

    for (int kt = 0; kt < SEQ; kt += 64) {
#pragma unroll
        for (int t = 0; t < 4; t++) {
            int idx = tid + t * 256;
            int r = idx >> 4;
            int dq = (idx & 15) << 2;
            float4 k4 = *(const float4*)&kg[(kt + r) * DK + dq];
            float kk[4] = {k4.x, k4.y, k4.z, k4.w};
#pragma unroll
            for (int u = 0; u < 4; u++) {
                int d = dq + u;
                KVs[d * 64 + (r ^ ((d & 15) << 2))] = kk[u];
            }
        }
        __syncthreads();

        float s[4][4];
#pragma unroll
        for (int i = 0; i < 4; i++)
#pragma unroll
            for (int j = 0; j < 4; j++) s[i][j] = 0.0f;

#pragma unroll 4
        for (int d = 0; d < 64; d++) {
            int swz = (d & 15) << 2;
            float4 q4 = *(float4*)&Qst[d * 64 + ((4 * ty) ^ swz)];
            float4 k4 = *(float4*)&KVs[d * 64 + ((4 * tx) ^ swz)];
            float qa[4] = {q4.x, q4.y, q4.z, q4.w};
            float ka[4] = {k4.x, k4.y, k4.z, k4.w};
#pragma unroll
            for (int i = 0; i < 4; i++)
#pragma unroll
                for (int j = 0; j < 4; j++)
                    s[i][j] = fmaf(qa[i], ka[j], s[i][j]);
        }

#pragma unroll
        for (int i = 0; i < 4; i++) {
            float tm = -1e30f;
#pragma unroll
            for (int j = 0; j < 4; j++) { s[i][j] *= 0.125f; tm = fmaxf(tm, s[i][j]); }
            tm = redmax16(tm);
            float mn = fmaxf(mrow[i], tm);
            float al = __expf(mrow[i] - mn);
            float rs = 0.0f;
#pragma unroll
            for (int j = 0; j < 4; j++) { s[i][j] = __expf(s[i][j] - mn); rs += s[i][j]; }
            rs = redsum16(rs);
            lrow[i] = lrow[i] * al + rs;
            mrow[i] = mn;
#pragma unroll
            for (int j = 0; j < 4; j++) acc[i][j] *= al;
            float4 p4; p4.x = s[i][0]; p4.y = s[i][1]; p4.z = s[i][2]; p4.w = s[i][3];
            *(float4*)&Ps[(4 * ty + i) * 64 + 4 * tx] = p4;
        }
        __syncthreads();

#pragma unroll
        for (int t = 0; t < 4; t++) {
            int idx = tid + t * 256;
            int r = idx >> 4;
            int dq = (idx & 15) << 2;
            float4 v4 = *(const float4*)&vg[(kt + r) * DK + dq];
            *(float4*)&KVs[r * DK + dq] = v4;
        }
        __syncthreads();

#pragma unroll 4
        for (int k = 0; k < 64; k++) {
            float4 v4 = *(float4*)&KVs[k * 64 + 4 * tx];
#pragma unroll
            for (int i = 0; i < 4; i++) {
                float p = Ps[(4 * ty + i) * 64 + k];
                acc[i][0] = fmaf(p, v4.x, acc[i][0]);
                acc[i][1] = fmaf(p, v4.y, acc[i][1]);
                acc[i][2] = fmaf(p, v4.z, acc[i][2]);
                acc[i][3] = fmaf(p, v4.w, acc[i][3]);
            }
        }
        __syncthreads();
    }

    const int b = bh >> 4, h = bh & 15;
#pragma unroll
    for (int i = 0; i < 4; i++) {
        float inv = 1.0f / lrow[i];
        int row = q0 + 4 * ty + i;
        float4 o;
        o.x = acc[i][0] * inv; o.y = acc[i][1] * inv;
        o.z = acc[i][2] * inv; o.w = acc[i][3] * inv;
        *(float4*)&g_ctx[(b * SEQ + row) * DMODEL + h * 64 + 4 * tx] = o;
    }
}

// ---------------------------------------------------------------------------
extern "C" void kernel_launch(void* const* d_in, const int* in_sizes, int n_in,
                              void* d_out, int out_size)
{
    (void)in_sizes; (void)n_in; (void)out_size;
    const float* q  = (const float*)d_in[0];
    const float* k  = (const float*)d_in[1];
    const float* v  = (const float*)d_in[2];
    const float* Wq = (const float*)d_in[3];
    const float* bq = (const float*)d_in[4];
    const float* Wk = (const float*)d_in[5];
    const float* bk = (const float*)d_in[6];
    const float* Wv = (const float*)d_in[7];
    const float* bv = (const float*)d_in[8];
    const float* Wo = (const float*)d_in[9];
    const float* bo = (const float*)d_in[10];
    float* out = (float*)d_out;

    float *gq, *gk, *gv, *gctx;
    cudaGetSymbolAddress((void**)&gq,   g_q);
    cudaGetSymbolAddress((void**)&gk,   g_k);
    cudaGetSymbolAddress((void**)&gv,   g_v);
    cudaGetSymbolAddress((void**)&gctx, g_ctx);

    __nv_bfloat16 *qh, *ql, *kh, *kl, *vh, *vl, *ch, *cl, *wh, *wl;
    cudaGetSymbolAddress((void**)&qh, s_qh); cudaGetSymbolAddress((void**)&ql, s_ql);
    cudaGetSymbolAddress((void**)&kh, s_kh); cudaGetSymbolAddress((void**)&kl, s_kl);
    cudaGetSymbolAddress((void**)&vh, s_vh); cudaGetSymbolAddress((void**)&vl, s_vl);
    cudaGetSymbolAddress((void**)&ch, s_ch); cudaGetSymbolAddress((void**)&cl, s_cl);
    cudaGetSymbolAddress((void**)&wh, s_wh); cudaGetSymbolAddress((void**)&wl, s_wl);

    const size_t WSZ = (size_t)DMODEL * DMODEL;
    const int NX4 = MROWS * DMODEL / 4;
    const int NW4 = DMODEL * DMODEL / 4;
    split_kernel<<<NX4 / 256, 256>>>(q, qh, ql, NX4);
    split_kernel<<<NX4 / 256, 256>>>(k, kh, kl, NX4);
    split_kernel<<<NX4 / 256, 256>>>(v, vh, vl, NX4);
    split_kernel<<<NW4 / 256, 256>>>(Wq, wh + 0 * WSZ, wl + 0 * WSZ, NW4);
    split_kernel<<<NW4 / 256, 256>>>(Wk, wh + 1 * WSZ, wl + 1 * WSZ, NW4);
    split_kernel<<<NW4 / 256, 256>>>(Wv, wh + 2 * WSZ, wl + 2 * WSZ, NW4);
    split_kernel<<<NW4 / 256, 256>>>(Wo, wh + 3 * WSZ, wl + 3 * WSZ, NW4);

    dim3 gg(DMODEL / 128, MROWS / 128);  // (8, 32)
    gemm_mma<1><<<gg, 256>>>(qh, ql, wh + 0 * WSZ, wl + 0 * WSZ, bq, gq);
    gemm_mma<1><<<gg, 256>>>(kh, kl, wh + 1 * WSZ, wl + 1 * WSZ, bk, gk);
    gemm_mma<1><<<gg, 256>>>(vh, vl, wh + 2 * WSZ, wl + 2 * WSZ, bv, gv);

    attn_kernel<<<dim3(BHN, SEQ / 64), 256>>>();

    split_kernel<<<NX4 / 256, 256>>>(gctx, ch, cl, NX4);
    gemm_mma<0><<<gg, 256>>>(ch, cl, wh + 3 * WSZ, wl + 3 * WSZ, bo, out);
}

// round 4
// speedup vs baseline: 2.5138x; 1.8749x over previous
#include <cuda_runtime.h>
#include <cuda_bf16.h>
#include <cstdint>
#include <math.h>

#define H 16
#define DMODEL 1024
#define DK 64
#define NB 2
#define SEQ 2048
#define MROWS (NB*SEQ)   // 4096
#define BHN (NB*H)       // 32

// ---------------- scratch (device globals; no allocation allowed) ----------
__device__ __nv_bfloat16 s_qh[MROWS * DMODEL], s_ql[MROWS * DMODEL];
__device__ __nv_bfloat16 s_kh[MROWS * DMODEL], s_kl[MROWS * DMODEL];
__device__ __nv_bfloat16 s_vh[MROWS * DMODEL], s_vl[MROWS * DMODEL];
__device__ __nv_bfloat16 s_ch[MROWS * DMODEL], s_cl[MROWS * DMODEL];
__device__ __nv_bfloat16 s_wh[4][DMODEL * DMODEL], s_wl[4][DMODEL * DMODEL];

// attention operands (head layout / transposed), bf16 hi+lo
__device__ __nv_bfloat16 a_qh[BHN * SEQ * DK], a_ql[BHN * SEQ * DK];
__device__ __nv_bfloat16 a_kh[BHN * SEQ * DK], a_kl[BHN * SEQ * DK];
__device__ __nv_bfloat16 a_vth[BHN * DK * SEQ], a_vtl[BHN * DK * SEQ];

// ---------------- helpers ---------------------------------------------------
static __device__ __forceinline__ uint32_t smem_u32(const void* p) {
    uint32_t a;
    asm("{ .reg .u64 t; cvta.to.shared.u64 t, %1; cvt.u32.u64 %0, t; }"
        : "=r"(a) : "l"(p));
    return a;
}
static __device__ __forceinline__ void cp16(uint32_t s, const void* g) {
    asm volatile("cp.async.cg.shared.global [%0], [%1], 16;" :: "r"(s), "l"(g));
}
#define CP_COMMIT() asm volatile("cp.async.commit_group;")
template <int N>
static __device__ __forceinline__ void cp_wait() {
    asm volatile("cp.async.wait_group %0;" :: "n"(N));
}
static __device__ __forceinline__ void ldm_x4(uint32_t& r0, uint32_t& r1,
                                              uint32_t& r2, uint32_t& r3, uint32_t a) {
    asm volatile("ldmatrix.sync.aligned.m8n8.x4.shared.b16 {%0,%1,%2,%3}, [%4];"
                 : "=r"(r0), "=r"(r1), "=r"(r2), "=r"(r3) : "r"(a));
}
static __device__ __forceinline__ void mma_bf16(float* c, const uint32_t* a,
                                                const uint32_t* b) {
    asm volatile(
        "mma.sync.aligned.m16n8k16.row.col.f32.bf16.bf16.f32 "
        "{%0,%1,%2,%3}, {%4,%5,%6,%7}, {%8,%9}, {%0,%1,%2,%3};"
        : "+f"(c[0]), "+f"(c[1]), "+f"(c[2]), "+f"(c[3])
        : "r"(a[0]), "r"(a[1]), "r"(a[2]), "r"(a[3]), "r"(b[0]), "r"(b[1]));
}
static __device__ __forceinline__ float ex2(float x) {
    float y; asm("ex2.approx.f32 %0, %1;" : "=f"(y) : "f"(x)); return y;
}
// pack two floats -> bf16x2 hi and bf16x2 lo (residual)
static __device__ __forceinline__ void packhl(float a, float b,
                                              uint32_t& hi, uint32_t& lo) {
    __nv_bfloat16 ah = __float2bfloat16(a), bh = __float2bfloat16(b);
    __nv_bfloat16 al = __float2bfloat16(a - __bfloat162float(ah));
    __nv_bfloat16 bl = __float2bfloat16(b - __bfloat162float(bh));
    __nv_bfloat162 h2; h2.x = ah; h2.y = bh;
    __nv_bfloat162 l2; l2.x = al; l2.y = bl;
    hi = *(uint32_t*)&h2; lo = *(uint32_t*)&l2;
}

// ---------------------------------------------------------------------------
// split fp32 -> bf16 hi + bf16 lo
// ---------------------------------------------------------------------------
__global__ void split_kernel(const float* __restrict__ x,
                             __nv_bfloat16* __restrict__ hi,
                             __nv_bfloat16* __restrict__ lo, int n4)
{
    int i = blockIdx.x * 256 + threadIdx.x;
    if (i >= n4) return;
    float4 v = ((const float4*)x)[i];
    float vv[4] = {v.x, v.y, v.z, v.w};
    uint32_t h2[2], l2[2];
    packhl(vv[0], vv[1], h2[0], l2[0]);
    packhl(vv[2], vv[3], h2[1], l2[1]);
    ((uint32_t*)hi)[2 * i] = h2[0];
    ((uint32_t*)hi)[2 * i + 1] = h2[1];
    ((uint32_t*)lo)[2 * i] = l2[0];
    ((uint32_t*)lo)[2 * i + 1] = l2[1];
}

// ---------------------------------------------------------------------------
// mma.sync split-bf16 GEMM (validated R3). Epilogue modes:
//   0: fp32 flat Y[m][n]
//   1: bf16 hi/lo head layout  [((b*H+h)*SEQ+s)*64 + d]
//   2: bf16 hi/lo transposed   [((b*H+h)*64 + d)*SEQ + s]
// ---------------------------------------------------------------------------
#define NIT 96

template <int MODE>
__global__ void __launch_bounds__(256, 2)
gemm_mma(const __nv_bfloat16* __restrict__ Ah, const __nv_bfloat16* __restrict__ Al,
         const __nv_bfloat16* __restrict__ Bh, const __nv_bfloat16* __restrict__ Bl,
         const float* __restrict__ bias, float* __restrict__ Y,
         __nv_bfloat16* __restrict__ Yh, __nv_bfloat16* __restrict__ Yl)
{
    __shared__ __align__(128) char smA[2][128 * 64];
    __shared__ __align__(128) char smB[2][128 * 64];

    const int tid = threadIdx.x;
    const int wid = tid >> 5, lane = tid & 31;
    const int wm = wid >> 2, wn = wid & 3;
    const int m0 = blockIdx.y << 7, n0 = blockIdx.x << 7;

    const uint32_t sA0 = smem_u32(smA[0]), sA1 = smem_u32(smA[1]);
    const uint32_t sB0 = smem_u32(smB[0]), sB1 = smem_u32(smB[1]);

    float acc[4][4][4];
#pragma unroll
    for (int i = 0; i < 4; i++)
#pragma unroll
        for (int j = 0; j < 4; j++)
#pragma unroll
            for (int u = 0; u < 4; u++) acc[i][j][u] = 0.0f;

    const int r0c = tid >> 2, b0c = tid & 3;
    const int r1c = (tid + 256) >> 2, b1c = tid & 3;
    const uint32_t o0 = (uint32_t)(r0c * 64 + ((b0c ^ (r0c & 3)) << 4));
    const uint32_t o1 = (uint32_t)(r1c * 64 + ((b1c ^ (r1c & 3)) << 4));

    auto load_it = [&](int it, int buf) {
        const int p = it >> 5;
        const int kk = (it & 31) << 5;
        const __nv_bfloat16* Ap = (p < 2) ? Ah : Al;
        const __nv_bfloat16* Bp = (p == 1) ? Bl : Bh;
        uint32_t da = buf ? sA1 : sA0;
        uint32_t db = buf ? sB1 : sB0;
        cp16(da + o0, Ap + (size_t)(m0 + r0c) * DMODEL + kk + b0c * 8);
        cp16(da + o1, Ap + (size_t)(m0 + r1c) * DMODEL + kk + b1c * 8);
        cp16(db + o0, Bp + (size_t)(n0 + r0c) * DMODEL + kk + b0c * 8);
        cp16(db + o1, Bp + (size_t)(n0 + r1c) * DMODEL + kk + b1c * 8);
        CP_COMMIT();
    };

    const int arow = wm * 64 + (lane & 15);
    const int abit = lane >> 4;
    const int brow = wn * 32 + (lane & 7) + ((lane >> 4) & 1) * 8;
    const int bbit = (lane >> 3) & 1;

    load_it(0, 0);

    for (int it = 0; it < NIT; ++it) {
        if (it + 1 < NIT) load_it(it + 1, (it + 1) & 1);
        if (it + 1 < NIT) cp_wait<1>(); else cp_wait<0>();
        __syncthreads();

        const uint32_t da = (it & 1) ? sA1 : sA0;
        const uint32_t db = (it & 1) ? sB1 : sB0;

#pragma unroll
        for (int ks = 0; ks < 2; ks++) {
            uint32_t af[4][4], bf[2][4];
#pragma unroll
            for (int mt = 0; mt < 4; mt++) {
                int row = arow + mt * 16;
                int ch = 2 * ks + abit;
                uint32_t ad = da + (uint32_t)(row * 64 + ((ch ^ (row & 3)) << 4));
                ldm_x4(af[mt][0], af[mt][1], af[mt][2], af[mt][3], ad);
            }
#pragma unroll
            for (int np = 0; np < 2; np++) {
                int row = brow + np * 16;
                int ch = 2 * ks + bbit;
                uint32_t bd = db + (uint32_t)(row * 64 + ((ch ^ (row & 3)) << 4));
                ldm_x4(bf[np][0], bf[np][1], bf[np][2], bf[np][3], bd);
            }
#pragma unroll
            for (int mt = 0; mt < 4; mt++)
#pragma unroll
                for (int nt = 0; nt < 4; nt++)
                    mma_bf16(acc[mt][nt], af[mt], bf[nt >> 1] + (nt & 1) * 2);
        }
        __syncthreads();
    }

    // ---- epilogue ----
    const int ml = lane >> 2;
    const int nl = (lane & 3) << 1;
#pragma unroll
    for (int mt = 0; mt < 4; mt++) {
#pragma unroll
        for (int half = 0; half < 2; half++) {
            int m = m0 + wm * 64 + mt * 16 + ml + half * 8;
#pragma unroll
            for (int nt = 0; nt < 4; nt++) {
                int n = n0 + wn * 32 + nt * 8 + nl;
                float x = acc[mt][nt][2 * half + 0] + bias[n + 0];
                float y = acc[mt][nt][2 * half + 1] + bias[n + 1];
                if (MODE == 0) {
                    float2 o; o.x = x; o.y = y;
                    *(float2*)&Y[(size_t)m * DMODEL + n] = o;
                } else {
                    int bb = m >> 11, s = m & 2047;
                    int h = n >> 6, d = n & 63;
                    uint32_t hi, lo;
                    packhl(x, y, hi, lo);
                    if (MODE == 1) {
                        size_t idx = (size_t)((bb * H + h) * SEQ + s) * DK + d;
                        *(uint32_t*)&Yh[idx] = hi;
                        *(uint32_t*)&Yl[idx] = lo;
                    } else {
                        __nv_bfloat162 h2 = *(__nv_bfloat162*)&hi;
                        __nv_bfloat162 l2 = *(__nv_bfloat162*)&lo;
                        size_t base = (size_t)((bb * H + h) * DK + d) * SEQ + s;
                        Yh[base] = h2.x; Yh[base + SEQ] = h2.y;
                        Yl[base] = l2.x; Yl[base + SEQ] = l2.y;
                    }
                }
            }
        }
    }
}

// ---------------------------------------------------------------------------
// Tensor-core flash attention, split-bf16.
// BQ=128, BKV=64, 8 warps x 16 q-rows. Q resident in registers (hi+lo frags);
// K/Vt streamed double-buffered via cp.async. Softmax in base-2 domain.
// Smem: Qh 16K | Ql 16K | 2 x (Kh 8K | Kl 8K | Vh 8K | Vl 8K) = 96KB dynamic.
// Epilogue writes ctx as bf16 hi/lo flat [b*S+s][h*64+d] for the O-proj GEMM.
// ---------------------------------------------------------------------------
__global__ void __launch_bounds__(256)
attn_mma()
{
    extern __shared__ char dsm[];
    const uint32_t sbase = smem_u32(dsm);
    const uint32_t sQh = sbase, sQl = sbase + 16384;
    const uint32_t sKV = sbase + 32768;           // + buf*32768

    const int bh = blockIdx.x;
    const int q0 = blockIdx.y << 7;
    const int tid = threadIdx.x, wid = tid >> 5, lane = tid & 31;

    const __nv_bfloat16* qhg = a_qh + (size_t)bh * SEQ * DK;
    const __nv_bfloat16* qlg = a_ql + (size_t)bh * SEQ * DK;
    const __nv_bfloat16* khg = a_kh + (size_t)bh * SEQ * DK;
    const __nv_bfloat16* klg = a_kl + (size_t)bh * SEQ * DK;
    const __nv_bfloat16* vhg = a_vth + (size_t)bh * DK * SEQ;
    const __nv_bfloat16* vlg = a_vtl + (size_t)bh * DK * SEQ;

    // ---- load Q tile (hi+lo), 2 panels of 128x32 each ----
#pragma unroll
    for (int j = 0; j < 4; j++) {
        int cid = tid + 256 * j;          // 0..1023 16B chunks
        int hr = cid >> 2, c = cid & 3;   // hr = panel*128 + qrow
        int qrow = hr & 127, panel = hr >> 7;
        uint32_t off = (uint32_t)(hr * 64 + ((c ^ (hr & 3)) << 4));
        const size_t src = (size_t)(q0 + qrow) * DK + panel * 32 + c * 8;
        cp16(sQh + off, qhg + src);
        cp16(sQl + off, qlg + src);
    }
    CP_COMMIT();
    cp_wait<0>();
    __syncthreads();

    // ---- per-warp Q fragments (resident) ----
    uint32_t fQh[4][4], fQl[4][4];
    {
        const int row = wid * 16 + (lane & 15);
#pragma unroll
        for (int kf = 0; kf < 4; kf++) {
            int ch = ((kf & 1) << 1) + (lane >> 4);
            uint32_t off = (uint32_t)((kf >> 1) * 8192 + row * 64 + ((ch ^ (row & 3)) << 4));
            ldm_x4(fQh[kf][0], fQh[kf][1], fQh[kf][2], fQh[kf][3], sQh + off);
            ldm_x4(fQl[kf][0], fQl[kf][1], fQl[kf][2], fQl[kf][3], sQl + off);
        }
    }

    float ctxa[8][4];
#pragma unroll
    for (int i = 0; i < 8; i++)
#pragma unroll
        for (int u = 0; u < 4; u++) ctxa[i][u] = 0.0f;
    float mrun[2] = {-1e30f, -1e30f};
    float lrun[2] = {0.0f, 0.0f};

    // KV loader: 4 arrays x 512 chunks; 8 cp16/thread
    auto load_kv = [&](int kt, int buf) {
        uint32_t base = sKV + buf * 32768;
#pragma unroll
        for (int j = 0; j < 2; j++) {
            int cid = tid + 256 * j;
            int hr = cid >> 2, c = cid & 3;
            uint32_t off = (uint32_t)(hr * 64 + ((c ^ (hr & 3)) << 4));
            int lo6 = hr & 63, pan = hr >> 6;
            size_t ksrc = (size_t)(kt + lo6) * DK + pan * 32 + c * 8;
            size_t vsrc = (size_t)lo6 * SEQ + kt + pan * 32 + c * 8;
            cp16(base + off, khg + ksrc);
            cp16(base + 8192 + off, klg + ksrc);
            cp16(base + 16384 + off, vhg + vsrc);
            cp16(base + 24576 + off, vlg + vsrc);
        }
        CP_COMMIT();
    };

    const int brow = (lane & 7) + ((lane >> 4) & 1) * 8;
    const int bbit = (lane >> 3) & 1;
    const float C2 = 0.18033688f;   // log2(e)/8

    load_kv(0, 0);

    for (int t = 0; t < SEQ / 64; ++t) {
        if (t + 1 < SEQ / 64) { load_kv((t + 1) * 64, (t + 1) & 1); cp_wait<1>(); }
        else cp_wait<0>();
        __syncthreads();

        const uint32_t base = sKV + (t & 1) * 32768;

        // ---- S = Qh*Kh + Ql*Kh + Qh*Kl ----
        float sacc[8][4];
#pragma unroll
        for (int i = 0; i < 8; i++)
#pragma unroll
            for (int u = 0; u < 4; u++) sacc[i][u] = 0.0f;

#pragma unroll
        for (int kf = 0; kf < 4; kf++) {
#pragma unroll
            for (int np = 0; np < 4; np++) {
                int row = np * 16 + brow;
                int ch = ((kf & 1) << 1) + bbit;
                uint32_t off = (uint32_t)((kf >> 1) * 4096 + row * 64 + ((ch ^ (row & 3)) << 4));
                uint32_t kh4[4], kl4[4];
                ldm_x4(kh4[0], kh4[1], kh4[2], kh4[3], base + off);
                ldm_x4(kl4[0], kl4[1], kl4[2], kl4[3], base + 8192 + off);
                mma_bf16(sacc[2 * np], fQh[kf], kh4 + 0);
                mma_bf16(sacc[2 * np + 1], fQh[kf], kh4 + 2);
                mma_bf16(sacc[2 * np], fQl[kf], kh4 + 0);
                mma_bf16(sacc[2 * np + 1], fQl[kf], kh4 + 2);
                mma_bf16(sacc[2 * np], fQh[kf], kl4 + 0);
                mma_bf16(sacc[2 * np + 1], fQh[kf], kl4 + 2);
            }
        }

        // ---- online softmax (base-2 domain) ----
        float rmax0 = -1e30f, rmax1 = -1e30f;
#pragma unroll
        for (int i = 0; i < 8; i++) {
            rmax0 = fmaxf(rmax0, fmaxf(sacc[i][0], sacc[i][1]));
            rmax1 = fmaxf(rmax1, fmaxf(sacc[i][2], sacc[i][3]));
        }
        rmax0 = fmaxf(rmax0, __shfl_xor_sync(0xffffffffu, rmax0, 1));
        rmax0 = fmaxf(rmax0, __shfl_xor_sync(0xffffffffu, rmax0, 2));
        rmax1 = fmaxf(rmax1, __shfl_xor_sync(0xffffffffu, rmax1, 1));
        rmax1 = fmaxf(rmax1, __shfl_xor_sync(0xffffffffu, rmax1, 2));
        float mn0 = fmaxf(mrun[0], C2 * rmax0);
        float mn1 = fmaxf(mrun[1], C2 * rmax1);
        float al0 = ex2(mrun[0] - mn0);
        float al1 = ex2(mrun[1] - mn1);
        mrun[0] = mn0; mrun[1] = mn1;
#pragma unroll
        for (int i = 0; i < 8; i++) {
            ctxa[i][0] *= al0; ctxa[i][1] *= al0;
            ctxa[i][2] *= al1; ctxa[i][3] *= al1;
        }
        float rs0 = 0.0f, rs1 = 0.0f;
#pragma unroll
        for (int i = 0; i < 8; i++) {
            sacc[i][0] = ex2(fmaf(C2, sacc[i][0], -mn0));
            sacc[i][1] = ex2(fmaf(C2, sacc[i][1], -mn0));
            sacc[i][2] = ex2(fmaf(C2, sacc[i][2], -mn1));
            sacc[i][3] = ex2(fmaf(C2, sacc[i][3], -mn1));
            rs0 += sacc[i][0] + sacc[i][1];
            rs1 += sacc[i][2] + sacc[i][3];
        }
        rs0 += __shfl_xor_sync(0xffffffffu, rs0, 1);
        rs0 += __shfl_xor_sync(0xffffffffu, rs0, 2);
        rs1 += __shfl_xor_sync(0xffffffffu, rs1, 1);
        rs1 += __shfl_xor_sync(0xffffffffu, rs1, 2);
        lrun[0] = lrun[0] * al0 + rs0;
        lrun[1] = lrun[1] * al1 + rs1;

        // ---- ctx += Ph*Vh + Pl*Vh + Ph*Vl ----
#pragma unroll
        for (int kf = 0; kf < 4; kf++) {
            uint32_t pH[4], pL[4];
            packhl(sacc[2 * kf][0], sacc[2 * kf][1], pH[0], pL[0]);
            packhl(sacc[2 * kf][2], sacc[2 * kf][3], pH[1], pL[1]);
            packhl(sacc[2 * kf + 1][0], sacc[2 * kf + 1][1], pH[2], pL[2]);
            packhl(sacc[2 * kf + 1][2], sacc[2 * kf + 1][3], pH[3], pL[3]);
#pragma unroll
            for (int np = 0; np < 4; np++) {
                int row = np * 16 + brow;      // d index
                int ch = ((kf & 1) << 1) + bbit;
                uint32_t off = (uint32_t)((kf >> 1) * 4096 + row * 64 + ((ch ^ (row & 3)) << 4));
                uint32_t vh4[4], vl4[4];
                ldm_x4(vh4[0], vh4[1], vh4[2], vh4[3], base + 16384 + off);
                ldm_x4(vl4[0], vl4[1], vl4[2], vl4[3], base + 24576 + off);
                mma_bf16(ctxa[2 * np], pH, vh4 + 0);
                mma_bf16(ctxa[2 * np + 1], pH, vh4 + 2);
                mma_bf16(ctxa[2 * np], pL, vh4 + 0);
                mma_bf16(ctxa[2 * np + 1], pL, vh4 + 2);
                mma_bf16(ctxa[2 * np], pH, vl4 + 0);
                mma_bf16(ctxa[2 * np + 1], pH, vl4 + 2);
            }
        }
        __syncthreads();
    }

    // ---- epilogue: ctx/l -> bf16 hi/lo, flat [b*S+s][h*64+d] ----
    const float inv0 = 1.0f / lrun[0];
    const float inv1 = 1.0f / lrun[1];
    const int b = bh >> 4, h = bh & 15;
    const int r0 = q0 + wid * 16 + (lane >> 2);
    const int nl = (lane & 3) << 1;
#pragma unroll
    for (int nt = 0; nt < 8; nt++) {
        int d = nt * 8 + nl;
        uint32_t hi, lo;
        packhl(ctxa[nt][0] * inv0, ctxa[nt][1] * inv0, hi, lo);
        size_t i0 = (size_t)(b * SEQ + r0) * DMODEL + h * 64 + d;
        *(uint32_t*)&s_ch[i0] = hi;
        *(uint32_t*)&s_cl[i0] = lo;
        packhl(ctxa[nt][2] * inv1, ctxa[nt][3] * inv1, hi, lo);
        size_t i1 = (size_t)(b * SEQ + r0 + 8) * DMODEL + h * 64 + d;
        *(uint32_t*)&s_ch[i1] = hi;
        *(uint32_t*)&s_cl[i1] = lo;
    }
}

// ---------------------------------------------------------------------------
extern "C" void kernel_launch(void* const* d_in, const int* in_sizes, int n_in,
                              void* d_out, int out_size)
{
    (void)in_sizes; (void)n_in; (void)out_size;
    const float* q  = (const float*)d_in[0];
    const float* k  = (const float*)d_in[1];
    const float* v  = (const float*)d_in[2];
    const float* Wq = (const float*)d_in[3];
    const float* bq = (const float*)d_in[4];
    const float* Wk = (const float*)d_in[5];
    const float* bk = (const float*)d_in[6];
    const float* Wv = (const float*)d_in[7];
    const float* bv = (const float*)d_in[8];
    const float* Wo = (const float*)d_in[9];
    const float* bo = (const float*)d_in[10];
    float* out = (float*)d_out;

    __nv_bfloat16 *qh, *ql, *kh, *kl, *vh, *vl, *ch, *cl, *wh, *wl;
    __nv_bfloat16 *aqh, *aql, *akh, *akl, *avh, *avl;
    cudaGetSymbolAddress((void**)&qh, s_qh); cudaGetSymbolAddress((void**)&ql, s_ql);
    cudaGetSymbolAddress((void**)&kh, s_kh); cudaGetSymbolAddress((void**)&kl, s_kl);
    cudaGetSymbolAddress((void**)&vh, s_vh); cudaGetSymbolAddress((void**)&vl, s_vl);
    cudaGetSymbolAddress((void**)&ch, s_ch); cudaGetSymbolAddress((void**)&cl, s_cl);
    cudaGetSymbolAddress((void**)&wh, s_wh); cudaGetSymbolAddress((void**)&wl, s_wl);
    cudaGetSymbolAddress((void**)&aqh, a_qh); cudaGetSymbolAddress((void**)&aql, a_ql);
    cudaGetSymbolAddress((void**)&akh, a_kh); cudaGetSymbolAddress((void**)&akl, a_kl);
    cudaGetSymbolAddress((void**)&avh, a_vth); cudaGetSymbolAddress((void**)&avl, a_vtl);

    static bool attr_done = false;
    cudaFuncSetAttribute(attn_mma, cudaFuncAttributeMaxDynamicSharedMemorySize, 98304);
    (void)attr_done;

    const size_t WSZ = (size_t)DMODEL * DMODEL;
    const int NX4 = MROWS * DMODEL / 4;
    const int NW4 = DMODEL * DMODEL / 4;
    split_kernel<<<NX4 / 256, 256>>>(q, qh, ql, NX4);
    split_kernel<<<NX4 / 256, 256>>>(k, kh, kl, NX4);
    split_kernel<<<NX4 / 256, 256>>>(v, vh, vl, NX4);
    split_kernel<<<NW4 / 256, 256>>>(Wq, wh + 0 * WSZ, wl + 0 * WSZ, NW4);
    split_kernel<<<NW4 / 256, 256>>>(Wk, wh + 1 * WSZ, wl + 1 * WSZ, NW4);
    split_kernel<<<NW4 / 256, 256>>>(Wv, wh + 2 * WSZ, wl + 2 * WSZ, NW4);
    split_kernel<<<NW4 / 256, 256>>>(Wo, wh + 3 * WSZ, wl + 3 * WSZ, NW4);

    dim3 gg(DMODEL / 128, MROWS / 128);  // (8, 32)
    gemm_mma<1><<<gg, 256>>>(qh, ql, wh + 0 * WSZ, wl + 0 * WSZ, bq, nullptr, aqh, aql);
    gemm_mma<1><<<gg, 256>>>(kh, kl, wh + 1 * WSZ, wl + 1 * WSZ, bk, nullptr, akh, akl);
    gemm_mma<2><<<gg, 256>>>(vh, vl, wh + 2 * WSZ, wl + 2 * WSZ, bv, nullptr, avh, avl);

    attn_mma<<<dim3(BHN, SEQ / 128), 256, 98304>>>();

    gemm_mma<0><<<gg, 256>>>(ch, cl, wh + 3 * WSZ, wl + 3 * WSZ, bo, out, nullptr, nullptr);
}

// round 5
// speedup vs baseline: 2.9554x; 1.1757x over previous
#include <cuda_runtime.h>
#include <cuda_bf16.h>
#include <cstdint>
#include <math.h>

#define H 16
#define DMODEL 1024
#define DK 64
#define NB 2
#define SEQ 2048
#define MROWS (NB*SEQ)   // 4096
#define BHN (NB*H)       // 32

// ---------------- scratch (device globals; no allocation allowed) ----------
__device__ __nv_bfloat16 s_qh[MROWS * DMODEL], s_ql[MROWS * DMODEL];
__device__ __nv_bfloat16 s_kh[MROWS * DMODEL], s_kl[MROWS * DMODEL];
__device__ __nv_bfloat16 s_vh[MROWS * DMODEL], s_vl[MROWS * DMODEL];
__device__ __nv_bfloat16 s_ch[MROWS * DMODEL], s_cl[MROWS * DMODEL];
__device__ __nv_bfloat16 s_wh[4][DMODEL * DMODEL], s_wl[4][DMODEL * DMODEL];

// attention operands (head layout / transposed), bf16 hi+lo
__device__ __nv_bfloat16 a_qh[BHN * SEQ * DK], a_ql[BHN * SEQ * DK];
__device__ __nv_bfloat16 a_kh[BHN * SEQ * DK], a_kl[BHN * SEQ * DK];
__device__ __nv_bfloat16 a_vth[BHN * DK * SEQ], a_vtl[BHN * DK * SEQ];

// ---------------- helpers ---------------------------------------------------
static __device__ __forceinline__ uint32_t smem_u32(const void* p) {
    uint32_t a;
    asm("{ .reg .u64 t; cvta.to.shared.u64 t, %1; cvt.u32.u64 %0, t; }"
        : "=r"(a) : "l"(p));
    return a;
}
static __device__ __forceinline__ void cp16(uint32_t s, const void* g) {
    asm volatile("cp.async.cg.shared.global [%0], [%1], 16;" :: "r"(s), "l"(g));
}
#define CP_COMMIT() asm volatile("cp.async.commit_group;")
template <int N>
static __device__ __forceinline__ void cp_wait() {
    asm volatile("cp.async.wait_group %0;" :: "n"(N));
}
static __device__ __forceinline__ void ldm_x4(uint32_t& r0, uint32_t& r1,
                                              uint32_t& r2, uint32_t& r3, uint32_t a) {
    asm volatile("ldmatrix.sync.aligned.m8n8.x4.shared.b16 {%0,%1,%2,%3}, [%4];"
                 : "=r"(r0), "=r"(r1), "=r"(r2), "=r"(r3) : "r"(a));
}
static __device__ __forceinline__ void mma_bf16(float* c, const uint32_t* a,
                                                const uint32_t* b) {
    asm volatile(
        "mma.sync.aligned.m16n8k16.row.col.f32.bf16.bf16.f32 "
        "{%0,%1,%2,%3}, {%4,%5,%6,%7}, {%8,%9}, {%0,%1,%2,%3};"
        : "+f"(c[0]), "+f"(c[1]), "+f"(c[2]), "+f"(c[3])
        : "r"(a[0]), "r"(a[1]), "r"(a[2]), "r"(a[3]), "r"(b[0]), "r"(b[1]));
}
static __device__ __forceinline__ float ex2(float x) {
    float y; asm("ex2.approx.f32 %0, %1;" : "=f"(y) : "f"(x)); return y;
}
static __device__ __forceinline__ void packhl(float a, float b,
                                              uint32_t& hi, uint32_t& lo) {
    __nv_bfloat16 ah = __float2bfloat16(a), bh = __float2bfloat16(b);
    __nv_bfloat16 al = __float2bfloat16(a - __bfloat162float(ah));
    __nv_bfloat16 bl = __float2bfloat16(b - __bfloat162float(bh));
    __nv_bfloat162 h2; h2.x = ah; h2.y = bh;
    __nv_bfloat162 l2; l2.x = al; l2.y = bl;
    hi = *(uint32_t*)&h2; lo = *(uint32_t*)&l2;
}

// ---------------------------------------------------------------------------
// split fp32 -> bf16 hi + bf16 lo
// ---------------------------------------------------------------------------
__global__ void split_kernel(const float* __restrict__ x,
                             __nv_bfloat16* __restrict__ hi,
                             __nv_bfloat16* __restrict__ lo, int n4)
{
    int i = blockIdx.x * 256 + threadIdx.x;
    if (i >= n4) return;
    float4 v = ((const float4*)x)[i];
    uint32_t h2[2], l2[2];
    packhl(v.x, v.y, h2[0], l2[0]);
    packhl(v.z, v.w, h2[1], l2[1]);
    ((uint32_t*)hi)[2 * i] = h2[0];
    ((uint32_t*)hi)[2 * i + 1] = h2[1];
    ((uint32_t*)lo)[2 * i] = l2[0];
    ((uint32_t*)lo)[2 * i + 1] = l2[1];
}

// ---------------------------------------------------------------------------
// Split-bf16 GEMM, shared-staging restructure:
// per 32-wide k-chunk, stage Ah|Al|Bh|Bl (4 x 8KB) ONCE and run all three
// passes (Ah*Bh, Ah*Bl, Al*Bh) => 96 MMAs / 32KB staged (1.5x R4 ratio).
// 3-stage cp.async pipeline, one __syncthreads per iteration.
// Epilogue modes: 0 fp32 flat, 1 bf16 hi/lo head layout, 2 bf16 hi/lo
// transposed [((b*H+h)*64+d)*SEQ+s].
// ---------------------------------------------------------------------------
#define NIT2 32      // 1024 / 32

template <int MODE>
__global__ void __launch_bounds__(256, 2)
gemm_mma(const __nv_bfloat16* __restrict__ Ah, const __nv_bfloat16* __restrict__ Al,
         const __nv_bfloat16* __restrict__ Bh, const __nv_bfloat16* __restrict__ Bl,
         const float* __restrict__ bias, float* __restrict__ Y,
         __nv_bfloat16* __restrict__ Yh, __nv_bfloat16* __restrict__ Yl)
{
    extern __shared__ char dsm[];
    const uint32_t sS = smem_u32(dsm);     // 3 stages x 32KB: Ah|Al|Bh|Bl

    const int tid = threadIdx.x;
    const int wid = tid >> 5, lane = tid & 31;
    const int wm = wid >> 2, wn = wid & 3;
    const int m0 = blockIdx.y << 7, n0 = blockIdx.x << 7;

    float acc[4][4][4];
#pragma unroll
    for (int i = 0; i < 4; i++)
#pragma unroll
        for (int j = 0; j < 4; j++)
#pragma unroll
            for (int u = 0; u < 4; u++) acc[i][j][u] = 0.0f;

    // loader: 512 chunks per 8KB array; thread owns chunks tid, tid+256
    const int r0c = tid >> 2, b0c = tid & 3;
    const int r1c = (tid + 256) >> 2;
    const uint32_t o0 = (uint32_t)(r0c * 64 + ((b0c ^ (r0c & 3)) << 4));
    const uint32_t o1 = (uint32_t)(r1c * 64 + ((b0c ^ (r1c & 3)) << 4));
    const size_t ga0 = (size_t)(m0 + r0c) * DMODEL + b0c * 8;
    const size_t ga1 = (size_t)(m0 + r1c) * DMODEL + b0c * 8;
    const size_t gb0 = (size_t)(n0 + r0c) * DMODEL + b0c * 8;
    const size_t gb1 = (size_t)(n0 + r1c) * DMODEL + b0c * 8;

    auto load_it = [&](int it2, int st) {
        const int kk = it2 << 5;
        uint32_t b = sS + st * 32768;
        cp16(b + o0, Ah + ga0 + kk);
        cp16(b + o1, Ah + ga1 + kk);
        cp16(b + 8192 + o0, Al + ga0 + kk);
        cp16(b + 8192 + o1, Al + ga1 + kk);
        cp16(b + 16384 + o0, Bh + gb0 + kk);
        cp16(b + 16384 + o1, Bh + gb1 + kk);
        cp16(b + 24576 + o0, Bl + gb0 + kk);
        cp16(b + 24576 + o1, Bl + gb1 + kk);
        CP_COMMIT();
    };

    const int arow = wm * 64 + (lane & 15);
    const int abit = lane >> 4;
    const int brow = wn * 32 + (lane & 7) + ((lane >> 4) & 1) * 8;
    const int bbit = (lane >> 3) & 1;

    load_it(0, 0);
    load_it(1, 1);

    int st = 0;   // stage of iteration `it`
    for (int it = 0; it < NIT2; ++it) {
        if (it + 1 < NIT2) cp_wait<1>(); else cp_wait<0>();
        __syncthreads();
        if (it + 2 < NIT2) {
            int st2 = st + 2; if (st2 >= 3) st2 -= 3;
            load_it(it + 2, st2);
        }

        const uint32_t sb = sS + st * 32768;

#pragma unroll
        for (int ks = 0; ks < 2; ks++) {
            uint32_t bh4[2][4], bl4[2][4];
#pragma unroll
            for (int np = 0; np < 2; np++) {
                int row = brow + np * 16;
                int ch = 2 * ks + bbit;
                uint32_t off = (uint32_t)(row * 64 + ((ch ^ (row & 3)) << 4));
                ldm_x4(bh4[np][0], bh4[np][1], bh4[np][2], bh4[np][3], sb + 16384 + off);
                ldm_x4(bl4[np][0], bl4[np][1], bl4[np][2], bl4[np][3], sb + 24576 + off);
            }
            {
                uint32_t af[4][4];
#pragma unroll
                for (int mt = 0; mt < 4; mt++) {
                    int row = arow + mt * 16;
                    int ch = 2 * ks + abit;
                    uint32_t ad = sb + (uint32_t)(row * 64 + ((ch ^ (row & 3)) << 4));
                    ldm_x4(af[mt][0], af[mt][1], af[mt][2], af[mt][3], ad);
                }
#pragma unroll
                for (int mt = 0; mt < 4; mt++)
#pragma unroll
                    for (int nt = 0; nt < 4; nt++)
                        mma_bf16(acc[mt][nt], af[mt], bh4[nt >> 1] + (nt & 1) * 2);
#pragma unroll
                for (int mt = 0; mt < 4; mt++)
#pragma unroll
                    for (int nt = 0; nt < 4; nt++)
                        mma_bf16(acc[mt][nt], af[mt], bl4[nt >> 1] + (nt & 1) * 2);
            }
            {
                uint32_t al4[4][4];
#pragma unroll
                for (int mt = 0; mt < 4; mt++) {
                    int row = arow + mt * 16;
                    int ch = 2 * ks + abit;
                    uint32_t ad = sb + 8192 + (uint32_t)(row * 64 + ((ch ^ (row & 3)) << 4));
                    ldm_x4(al4[mt][0], al4[mt][1], al4[mt][2], al4[mt][3], ad);
                }
#pragma unroll
                for (int mt = 0; mt < 4; mt++)
#pragma unroll
                    for (int nt = 0; nt < 4; nt++)
                        mma_bf16(acc[mt][nt], al4[mt], bh4[nt >> 1] + (nt & 1) * 2);
            }
        }
        if (++st == 3) st = 0;
    }

    // ---- epilogue ----
    const int ml = lane >> 2;
    const int nl = (lane & 3) << 1;
#pragma unroll
    for (int mt = 0; mt < 4; mt++) {
#pragma unroll
        for (int half = 0; half < 2; half++) {
            int m = m0 + wm * 64 + mt * 16 + ml + half * 8;
#pragma unroll
            for (int nt = 0; nt < 4; nt++) {
                int n = n0 + wn * 32 + nt * 8 + nl;
                float x = acc[mt][nt][2 * half + 0] + bias[n + 0];
                float y = acc[mt][nt][2 * half + 1] + bias[n + 1];
                if (MODE == 0) {
                    float2 o; o.x = x; o.y = y;
                    *(float2*)&Y[(size_t)m * DMODEL + n] = o;
                } else {
                    int bb = m >> 11, s = m & 2047;
                    int h = n >> 6, d = n & 63;
                    uint32_t hi, lo;
                    packhl(x, y, hi, lo);
                    if (MODE == 1) {
                        size_t idx = (size_t)((bb * H + h) * SEQ + s) * DK + d;
                        *(uint32_t*)&Yh[idx] = hi;
                        *(uint32_t*)&Yl[idx] = lo;
                    } else {
                        __nv_bfloat162 h2 = *(__nv_bfloat162*)&hi;
                        __nv_bfloat162 l2 = *(__nv_bfloat162*)&lo;
                        size_t base = (size_t)((bb * H + h) * DK + d) * SEQ + s;
                        Yh[base] = h2.x; Yh[base + SEQ] = h2.y;
                        Yl[base] = l2.x; Yl[base + SEQ] = l2.y;
                    }
                }
            }
        }
    }
}

// ---------------------------------------------------------------------------
// Tensor-core flash attention, split-bf16 (unchanged from R4 passing version)
// ---------------------------------------------------------------------------
__global__ void __launch_bounds__(256)
attn_mma()
{
    extern __shared__ char dsm[];
    const uint32_t sbase = smem_u32(dsm);
    const uint32_t sQh = sbase, sQl = sbase + 16384;
    const uint32_t sKV = sbase + 32768;

    const int bh = blockIdx.x;
    const int q0 = blockIdx.y << 7;
    const int tid = threadIdx.x, wid = tid >> 5, lane = tid & 31;

    const __nv_bfloat16* qhg = a_qh + (size_t)bh * SEQ * DK;
    const __nv_bfloat16* qlg = a_ql + (size_t)bh * SEQ * DK;
    const __nv_bfloat16* khg = a_kh + (size_t)bh * SEQ * DK;
    const __nv_bfloat16* klg = a_kl + (size_t)bh * SEQ * DK;
    const __nv_bfloat16* vhg = a_vth + (size_t)bh * DK * SEQ;
    const __nv_bfloat16* vlg = a_vtl + (size_t)bh * DK * SEQ;

#pragma unroll
    for (int j = 0; j < 4; j++) {
        int cid = tid + 256 * j;
        int hr = cid >> 2, c = cid & 3;
        int qrow = hr & 127, panel = hr >> 7;
        uint32_t off = (uint32_t)(hr * 64 + ((c ^ (hr & 3)) << 4));
        const size_t src = (size_t)(q0 + qrow) * DK + panel * 32 + c * 8;
        cp16(sQh + off, qhg + src);
        cp16(sQl + off, qlg + src);
    }
    CP_COMMIT();
    cp_wait<0>();
    __syncthreads();

    uint32_t fQh[4][4], fQl[4][4];
    {
        const int row = wid * 16 + (lane & 15);
#pragma unroll
        for (int kf = 0; kf < 4; kf++) {
            int ch = ((kf & 1) << 1) + (lane >> 4);
            uint32_t off = (uint32_t)((kf >> 1) * 8192 + row * 64 + ((ch ^ (row & 3)) << 4));
            ldm_x4(fQh[kf][0], fQh[kf][1], fQh[kf][2], fQh[kf][3], sQh + off);
            ldm_x4(fQl[kf][0], fQl[kf][1], fQl[kf][2], fQl[kf][3], sQl + off);
        }
    }

    float ctxa[8][4];
#pragma unroll
    for (int i = 0; i < 8; i++)
#pragma unroll
        for (int u = 0; u < 4; u++) ctxa[i][u] = 0.0f;
    float mrun[2] = {-1e30f, -1e30f};
    float lrun[2] = {0.0f, 0.0f};

    auto load_kv = [&](int kt, int buf) {
        uint32_t base = sKV + buf * 32768;
#pragma unroll
        for (int j = 0; j < 2; j++) {
            int cid = tid + 256 * j;
            int hr = cid >> 2, c = cid & 3;
            uint32_t off = (uint32_t)(hr * 64 + ((c ^ (hr & 3)) << 4));
            int lo6 = hr & 63, pan = hr >> 6;
            size_t ksrc = (size_t)(kt + lo6) * DK + pan * 32 + c * 8;
            size_t vsrc = (size_t)lo6 * SEQ + kt + pan * 32 + c * 8;
            cp16(base + off, khg + ksrc);
            cp16(base + 8192 + off, klg + ksrc);
            cp16(base + 16384 + off, vhg + vsrc);
            cp16(base + 24576 + off, vlg + vsrc);
        }
        CP_COMMIT();
    };

    const int brow = (lane & 7) + ((lane >> 4) & 1) * 8;
    const int bbit = (lane >> 3) & 1;
    const float C2 = 0.18033688f;

    load_kv(0, 0);

    for (int t = 0; t < SEQ / 64; ++t) {
        if (t + 1 < SEQ / 64) { load_kv((t + 1) * 64, (t + 1) & 1); cp_wait<1>(); }
        else cp_wait<0>();
        __syncthreads();

        const uint32_t base = sKV + (t & 1) * 32768;

        float sacc[8][4];
#pragma unroll
        for (int i = 0; i < 8; i++)
#pragma unroll
            for (int u = 0; u < 4; u++) sacc[i][u] = 0.0f;

#pragma unroll
        for (int kf = 0; kf < 4; kf++) {
#pragma unroll
            for (int np = 0; np < 4; np++) {
                int row = np * 16 + brow;
                int ch = ((kf & 1) << 1) + bbit;
                uint32_t off = (uint32_t)((kf >> 1) * 4096 + row * 64 + ((ch ^ (row & 3)) << 4));
                uint32_t kh4[4], kl4[4];
                ldm_x4(kh4[0], kh4[1], kh4[2], kh4[3], base + off);
                ldm_x4(kl4[0], kl4[1], kl4[2], kl4[3], base + 8192 + off);
                mma_bf16(sacc[2 * np], fQh[kf], kh4 + 0);
                mma_bf16(sacc[2 * np + 1], fQh[kf], kh4 + 2);
                mma_bf16(sacc[2 * np], fQl[kf], kh4 + 0);
                mma_bf16(sacc[2 * np + 1], fQl[kf], kh4 + 2);
                mma_bf16(sacc[2 * np], fQh[kf], kl4 + 0);
                mma_bf16(sacc[2 * np + 1], fQh[kf], kl4 + 2);
            }
        }

        float rmax0 = -1e30f, rmax1 = -1e30f;
#pragma unroll
        for (int i = 0; i < 8; i++) {
            rmax0 = fmaxf(rmax0, fmaxf(sacc[i][0], sacc[i][1]));
            rmax1 = fmaxf(rmax1, fmaxf(sacc[i][2], sacc[i][3]));
        }
        rmax0 = fmaxf(rmax0, __shfl_xor_sync(0xffffffffu, rmax0, 1));
        rmax0 = fmaxf(rmax0, __shfl_xor_sync(0xffffffffu, rmax0, 2));
        rmax1 = fmaxf(rmax1, __shfl_xor_sync(0xffffffffu, rmax1, 1));
        rmax1 = fmaxf(rmax1, __shfl_xor_sync(0xffffffffu, rmax1, 2));
        float mn0 = fmaxf(mrun[0], C2 * rmax0);
        float mn1 = fmaxf(mrun[1], C2 * rmax1);
        float al0 = ex2(mrun[0] - mn0);
        float al1 = ex2(mrun[1] - mn1);
        mrun[0] = mn0; mrun[1] = mn1;
#pragma unroll
        for (int i = 0; i < 8; i++) {
            ctxa[i][0] *= al0; ctxa[i][1] *= al0;
            ctxa[i][2] *= al1; ctxa[i][3] *= al1;
        }
        float rs0 = 0.0f, rs1 = 0.0f;
#pragma unroll
        for (int i = 0; i < 8; i++) {
            sacc[i][0] = ex2(fmaf(C2, sacc[i][0], -mn0));
            sacc[i][1] = ex2(fmaf(C2, sacc[i][1], -mn0));
            sacc[i][2] = ex2(fmaf(C2, sacc[i][2], -mn1));
            sacc[i][3] = ex2(fmaf(C2, sacc[i][3], -mn1));
            rs0 += sacc[i][0] + sacc[i][1];
            rs1 += sacc[i][2] + sacc[i][3];
        }
        rs0 += __shfl_xor_sync(0xffffffffu, rs0, 1);
        rs0 += __shfl_xor_sync(0xffffffffu, rs0, 2);
        rs1 += __shfl_xor_sync(0xffffffffu, rs1, 1);
        rs1 += __shfl_xor_sync(0xffffffffu, rs1, 2);
        lrun[0] = lrun[0] * al0 + rs0;
        lrun[1] = lrun[1] * al1 + rs1;

#pragma unroll
        for (int kf = 0; kf < 4; kf++) {
            uint32_t pH[4], pL[4];
            packhl(sacc[2 * kf][0], sacc[2 * kf][1], pH[0], pL[0]);
            packhl(sacc[2 * kf][2], sacc[2 * kf][3], pH[1], pL[1]);
            packhl(sacc[2 * kf + 1][0], sacc[2 * kf + 1][1], pH[2], pL[2]);
            packhl(sacc[2 * kf + 1][2], sacc[2 * kf + 1][3], pH[3], pL[3]);
#pragma unroll
            for (int np = 0; np < 4; np++) {
                int row = np * 16 + brow;
                int ch = ((kf & 1) << 1) + bbit;
                uint32_t off = (uint32_t)((kf >> 1) * 4096 + row * 64 + ((ch ^ (row & 3)) << 4));
                uint32_t vh4[4], vl4[4];
                ldm_x4(vh4[0], vh4[1], vh4[2], vh4[3], base + 16384 + off);
                ldm_x4(vl4[0], vl4[1], vl4[2], vl4[3], base + 24576 + off);
                mma_bf16(ctxa[2 * np], pH, vh4 + 0);
                mma_bf16(ctxa[2 * np + 1], pH, vh4 + 2);
                mma_bf16(ctxa[2 * np], pL, vh4 + 0);
                mma_bf16(ctxa[2 * np + 1], pL, vh4 + 2);
                mma_bf16(ctxa[2 * np], pH, vl4 + 0);
                mma_bf16(ctxa[2 * np + 1], pH, vl4 + 2);
            }
        }
        __syncthreads();
    }

    const float inv0 = 1.0f / lrun[0];
    const float inv1 = 1.0f / lrun[1];
    const int b = bh >> 4, h = bh & 15;
    const int r0 = q0 + wid * 16 + (lane >> 2);
    const int nl = (lane & 3) << 1;
#pragma unroll
    for (int nt = 0; nt < 8; nt++) {
        int d = nt * 8 + nl;
        uint32_t hi, lo;
        packhl(ctxa[nt][0] * inv0, ctxa[nt][1] * inv0, hi, lo);
        size_t i0 = (size_t)(b * SEQ + r0) * DMODEL + h * 64 + d;
        *(uint32_t*)&s_ch[i0] = hi;
        *(uint32_t*)&s_cl[i0] = lo;
        packhl(ctxa[nt][2] * inv1, ctxa[nt][3] * inv1, hi, lo);
        size_t i1 = (size_t)(b * SEQ + r0 + 8) * DMODEL + h * 64 + d;
        *(uint32_t*)&s_ch[i1] = hi;
        *(uint32_t*)&s_cl[i1] = lo;
    }
}

// ---------------------------------------------------------------------------
extern "C" void kernel_launch(void* const* d_in, const int* in_sizes, int n_in,
                              void* d_out, int out_size)
{
    (void)in_sizes; (void)n_in; (void)out_size;
    const float* q  = (const float*)d_in[0];
    const float* k  = (const float*)d_in[1];
    const float* v  = (const float*)d_in[2];
    const float* Wq = (const float*)d_in[3];
    const float* bq = (const float*)d_in[4];
    const float* Wk = (const float*)d_in[5];
    const float* bk = (const float*)d_in[6];
    const float* Wv = (const float*)d_in[7];
    const float* bv = (const float*)d_in[8];
    const float* Wo = (const float*)d_in[9];
    const float* bo = (const float*)d_in[10];
    float* out = (float*)d_out;

    __nv_bfloat16 *qh, *ql, *kh, *kl, *vh, *vl, *ch, *cl, *wh, *wl;
    __nv_bfloat16 *aqh, *aql, *akh, *akl, *avh, *avl;
    cudaGetSymbolAddress((void**)&qh, s_qh); cudaGetSymbolAddress((void**)&ql, s_ql);
    cudaGetSymbolAddress((void**)&kh, s_kh); cudaGetSymbolAddress((void**)&kl, s_kl);
    cudaGetSymbolAddress((void**)&vh, s_vh); cudaGetSymbolAddress((void**)&vl, s_vl);
    cudaGetSymbolAddress((void**)&ch, s_ch); cudaGetSymbolAddress((void**)&cl, s_cl);
    cudaGetSymbolAddress((void**)&wh, s_wh); cudaGetSymbolAddress((void**)&wl, s_wl);
    cudaGetSymbolAddress((void**)&aqh, a_qh); cudaGetSymbolAddress((void**)&aql, a_ql);
    cudaGetSymbolAddress((void**)&akh, a_kh); cudaGetSymbolAddress((void**)&akl, a_kl);
    cudaGetSymbolAddress((void**)&avh, a_vth); cudaGetSymbolAddress((void**)&avl, a_vtl);

    const int GSM = 98304;   // 3 stages x 32KB
    cudaFuncSetAttribute(gemm_mma<0>, cudaFuncAttributeMaxDynamicSharedMemorySize, GSM);
    cudaFuncSetAttribute(gemm_mma<1>, cudaFuncAttributeMaxDynamicSharedMemorySize, GSM);
    cudaFuncSetAttribute(gemm_mma<2>, cudaFuncAttributeMaxDynamicSharedMemorySize, GSM);
    cudaFuncSetAttribute(attn_mma, cudaFuncAttributeMaxDynamicSharedMemorySize, 98304);

    const size_t WSZ = (size_t)DMODEL * DMODEL;
    const int NX4 = MROWS * DMODEL / 4;
    const int NW4 = DMODEL * DMODEL / 4;
    split_kernel<<<NX4 / 256, 256>>>(q, qh, ql, NX4);
    split_kernel<<<NX4 / 256, 256>>>(k, kh, kl, NX4);
    split_kernel<<<NX4 / 256, 256>>>(v, vh, vl, NX4);
    split_kernel<<<NW4 / 256, 256>>>(Wq, wh + 0 * WSZ, wl + 0 * WSZ, NW4);
    split_kernel<<<NW4 / 256, 256>>>(Wk, wh + 1 * WSZ, wl + 1 * WSZ, NW4);
    split_kernel<<<NW4 / 256, 256>>>(Wv, wh + 2 * WSZ, wl + 2 * WSZ, NW4);
    split_kernel<<<NW4 / 256, 256>>>(Wo, wh + 3 * WSZ, wl + 3 * WSZ, NW4);

    dim3 gg(DMODEL / 128, MROWS / 128);  // (8, 32)
    gemm_mma<1><<<gg, 256, GSM>>>(qh, ql, wh + 0 * WSZ, wl + 0 * WSZ, bq, nullptr, aqh, aql);
    gemm_mma<1><<<gg, 256, GSM>>>(kh, kl, wh + 1 * WSZ, wl + 1 * WSZ, bk, nullptr, akh, akl);
    gemm_mma<2><<<gg, 256, GSM>>>(vh, vl, wh + 2 * WSZ, wl + 2 * WSZ, bv, nullptr, avh, avl);

    attn_mma<<<dim3(BHN, SEQ / 128), 256, 98304>>>();

    gemm_mma<0><<<gg, 256, GSM>>>(ch, cl, wh + 3 * WSZ, wl + 3 * WSZ, bo, out, nullptr, nullptr);
}